// round 1
// baseline (speedup 1.0000x reference)
#include <cuda_runtime.h>

// Problem constants
#define Nn 64
#define Cc 64
#define Tt 300
#define Vv 25
#define Ss 3
#define Ii 16
#define TV 7500           // T*V
#define NS 192            // N*S
#define CNT_BN 480000.0f  // N*T*V per channel
#define EPS_BN 1e-5f

// ---------------- scratch (__device__ globals: allocation-free) ----------------
__device__ float g_a[(size_t)NS * Ii * TV];       // [n][s][i][t*v]   23.04M
__device__ float g_b[(size_t)NS * Ii * TV];       // [n][s][i][t*v]
__device__ float g_scores[NS * Vv * Vv];          // [n][s][v][w]
__device__ float g_adapt[NS * Vv * Vv];           // [n][s][v][w]
__device__ float g_z[(size_t)NS * Cc * TV];       // [n][k=s*64+c][t*w]  92.16M
__device__ float g_y[(size_t)Nn * Cc * TV];       // [n][o][t*w]
__device__ float g_wdt[Ss * Cc * Cc];             // [k][o]
__device__ float g_bdsum[Cc];
__device__ float g_stats[2 * Cc];                 // sum, sumsq per channel

// ---------------- K0: prep (transpose wd, bias sum, zero accumulators) --------
__global__ void k_prep(const float* __restrict__ wd, const float* __restrict__ bd) {
    int idx = blockIdx.x * 256 + threadIdx.x;
    if (idx < NS * Vv * Vv) g_scores[idx] = 0.f;
    if (idx < Ss * Cc * Cc) {
        int k = idx >> 6, o = idx & 63;
        int s = k >> 6, c = k & 63;
        g_wdt[idx] = wd[(s * 64 + o) * 64 + c];
    }
    if (idx < Cc) g_bdsum[idx] = bd[idx] + bd[64 + idx] + bd[128 + idx];
    if (idx < 2 * Cc) g_stats[idx] = 0.f;
}

// ---------------- K1: a = Wa@X + ba, b = Wb@X + bb  ([16,64]@[64,7500]) --------
// grid (192, 15), block 256. Each thread: 2 columns x 16 rows x {a,b}.
__global__ void k_ab(const float* __restrict__ x,
                     const float* __restrict__ wa, const float* __restrict__ ba,
                     const float* __restrict__ wb, const float* __restrict__ bb) {
    int ns = blockIdx.x;
    int n = ns / Ss, s = ns % Ss;
    __shared__ float was[Ii * Cc], wbs[Ii * Cc], bas[Ii], bbs[Ii];
    for (int j = threadIdx.x; j < Ii * Cc; j += 256) {
        was[j] = wa[s * Ii * Cc + j];
        wbs[j] = wb[s * Ii * Cc + j];
    }
    if (threadIdx.x < Ii) {
        bas[threadIdx.x] = ba[s * Ii + threadIdx.x];
        bbs[threadIdx.x] = bb[s * Ii + threadIdx.x];
    }
    __syncthreads();

    int col0 = blockIdx.y * 512 + threadIdx.x;
    int col1 = col0 + 256;
    bool ok1 = (col1 < TV);
    const float* xp = x + (size_t)n * Cc * TV;

    float aA0[Ii], aA1[Ii], aB0[Ii], aB1[Ii];
#pragma unroll
    for (int i = 0; i < Ii; i++) { aA0[i] = 0.f; aA1[i] = 0.f; aB0[i] = 0.f; aB1[i] = 0.f; }

    for (int c = 0; c < Cc; c++) {
        float x0 = xp[c * TV + col0];
        float x1 = ok1 ? xp[c * TV + col1] : 0.f;
#pragma unroll
        for (int i = 0; i < Ii; i++) {
            float wav = was[i * Cc + c], wbv = wbs[i * Cc + c];
            aA0[i] += wav * x0; aA1[i] += wav * x1;
            aB0[i] += wbv * x0; aB1[i] += wbv * x1;
        }
    }
    float* ap = g_a + (size_t)ns * Ii * TV;
    float* bp = g_b + (size_t)ns * Ii * TV;
#pragma unroll
    for (int i = 0; i < Ii; i++) {
        ap[i * TV + col0] = aA0[i] + bas[i];
        bp[i * TV + col0] = aB0[i] + bbs[i];
        if (ok1) {
            ap[i * TV + col1] = aA1[i] + bas[i];
            bp[i * TV + col1] = aB1[i] + bbs[i];
        }
    }
}

// ---------------- K2: scores[v,w] += sum_{i,t} a[i,t,v]*b[i,t,w] ---------------
// grid (192, 4) t-chunks of 75. block 256 (4 groups of 64; 49 active per group).
__global__ void k_scores() {
    int ns = blockIdx.x;
    int t0 = blockIdx.y * 75;
    __shared__ float at[Ii * 28], bt[Ii * 28], gsm[Vv * Vv];
    int tid = threadIdx.x;
    for (int j = tid; j < Vv * Vv; j += 256) gsm[j] = 0.f;

    int ig = tid >> 6, item = tid & 63;
    bool active = item < 49;
    int v0 = (item / 7) * 4, w0 = (item % 7) * 4;

    float greg[16];
#pragma unroll
    for (int r = 0; r < 16; r++) greg[r] = 0.f;

    const float* abase = g_a + (size_t)ns * Ii * TV;
    const float* bbase = g_b + (size_t)ns * Ii * TV;

    for (int t = t0; t < t0 + 75; t++) {
        __syncthreads();
        for (int j = tid; j < Ii * 28; j += 256) {
            int i = j / 28, cc = j - i * 28;
            at[j] = (cc < Vv) ? abase[i * TV + t * Vv + cc] : 0.f;
            bt[j] = (cc < Vv) ? bbase[i * TV + t * Vv + cc] : 0.f;
        }
        __syncthreads();
        if (active) {
#pragma unroll
            for (int ii = 0; ii < 4; ii++) {
                int i = ig * 4 + ii;
                float4 av = *(const float4*)&at[i * 28 + v0];
                float4 bv = *(const float4*)&bt[i * 28 + w0];
                greg[0]  += av.x * bv.x; greg[1]  += av.x * bv.y; greg[2]  += av.x * bv.z; greg[3]  += av.x * bv.w;
                greg[4]  += av.y * bv.x; greg[5]  += av.y * bv.y; greg[6]  += av.y * bv.z; greg[7]  += av.y * bv.w;
                greg[8]  += av.z * bv.x; greg[9]  += av.z * bv.y; greg[10] += av.z * bv.z; greg[11] += av.z * bv.w;
                greg[12] += av.w * bv.x; greg[13] += av.w * bv.y; greg[14] += av.w * bv.z; greg[15] += av.w * bv.w;
            }
        }
    }
    __syncthreads();
    if (active) {
#pragma unroll
        for (int r = 0; r < 4; r++)
#pragma unroll
            for (int cix = 0; cix < 4; cix++) {
                int v = v0 + r, w = w0 + cix;
                if (v < Vv && w < Vv) atomicAdd(&gsm[v * Vv + w], greg[r * 4 + cix]);
            }
    }
    __syncthreads();
    for (int j = tid; j < Vv * Vv; j += 256) atomicAdd(&g_scores[ns * Vv * Vv + j], gsm[j]);
}

// ---------------- K3: softmax over v (per column w) + adapt = A+W+attn --------
__global__ void k_softmax(const float* __restrict__ A, const float* __restrict__ W) {
    int ns = blockIdx.x;
    int s = ns % Ss;
    int w = threadIdx.x;
    if (w >= Vv) return;
    float col[Vv];
    const float inv = 1.f / 4800.f;
    float m = -1e30f;
#pragma unroll
    for (int v = 0; v < Vv; v++) {
        col[v] = g_scores[ns * Vv * Vv + v * Vv + w] * inv;
        m = fmaxf(m, col[v]);
    }
    float sum = 0.f;
#pragma unroll
    for (int v = 0; v < Vv; v++) { col[v] = __expf(col[v] - m); sum += col[v]; }
    float r = 1.f / sum;
#pragma unroll
    for (int v = 0; v < Vv; v++) {
        int off = s * Vv * Vv + v * Vv + w;
        g_adapt[ns * Vv * Vv + v * Vv + w] = A[off] + W[off] + col[v] * r;
    }
}

// ---------------- K4: z[n,s,c,t,w] = sum_v x[n,c,t,v]*adapt[n,s,v,w] ----------
// grid (192, 10) t-tiles of 32; block 256 = 8 warps; warp handles 8 c (2 at a time).
// dynamic smem: 640 (adapt) + 8*1600 (per-warp x/out staging) floats.
__global__ void k_z(const float* __restrict__ x) {
    extern __shared__ float sm[];
    float* ad = sm;            // 625 used, pad 640
    float* buf = sm + 640;     // 8 * 1600
    int ns = blockIdx.x;
    int n = ns / Ss;
    int tid = threadIdx.x;
    for (int j = tid; j < Vv * Vv; j += 256) ad[j] = g_adapt[ns * Vv * Vv + j];
    __syncthreads();

    int t0 = blockIdx.y * 32;
    int tt = min(32, Tt - t0);
    int wrp = tid >> 5, lane = tid & 31;
    float* wb = buf + wrp * 1600;

    for (int cp = 0; cp < 4; cp++) {
        int c0 = wrp * 8 + cp * 2;
        // stage x tiles for c0, c0+1 (coalesced)
#pragma unroll
        for (int cc = 0; cc < 2; cc++) {
            const float* xp = x + ((size_t)(n * Cc + c0 + cc) * Tt + t0) * Vv;
            for (int j = lane; j < tt * Vv; j += 32) wb[cc * 800 + j] = xp[j];
        }
        __syncwarp();
        float out0[Vv], out1[Vv];
        if (lane < tt) {
            float xv0[Vv], xv1[Vv];
#pragma unroll
            for (int v = 0; v < Vv; v++) {
                xv0[v] = wb[lane * Vv + v];
                xv1[v] = wb[800 + lane * Vv + v];
            }
            for (int w = 0; w < Vv; w++) {
                float a0 = 0.f, a1 = 0.f;
#pragma unroll
                for (int v = 0; v < Vv; v++) {
                    float av = ad[v * Vv + w];
                    a0 += xv0[v] * av;
                    a1 += xv1[v] * av;
                }
                out0[w] = a0; out1[w] = a1;
            }
        }
        __syncwarp();
        if (lane < tt) {
#pragma unroll
            for (int w = 0; w < Vv; w++) {
                wb[lane * Vv + w] = out0[w];
                wb[800 + lane * Vv + w] = out1[w];
            }
        }
        __syncwarp();
#pragma unroll
        for (int cc = 0; cc < 2; cc++) {
            float* zp = g_z + ((size_t)(ns * Cc + c0 + cc) * Tt + t0) * Vv;
            for (int j = lane; j < tt * Vv; j += 32) zp[j] = wb[cc * 800 + j];
        }
        __syncwarp();
    }
}

// ---------------- K5: y[n] = WDt^T[64,192] @ z[n][192,7500] + bdsum -----------
// grid (64, 59), block 256. BM=64, BN=128, BK=16; thread tile 8x4.
__global__ void k_gemm() {
    __shared__ float As[16][64];
    __shared__ float Bs[16][128];
    int n = blockIdx.x;
    int tw0 = blockIdx.y * 128;
    int tid = threadIdx.x;
    int ty = tid >> 5, tx = tid & 31;

    float acc[8][4];
#pragma unroll
    for (int r = 0; r < 8; r++)
#pragma unroll
        for (int q = 0; q < 4; q++) acc[r][q] = 0.f;

    const float* zb = g_z + (size_t)n * 192 * TV;

    for (int k0 = 0; k0 < 192; k0 += 16) {
        __syncthreads();
        for (int j = tid; j < 16 * 64; j += 256) {
            int kk = j >> 6, o = j & 63;
            As[kk][o] = g_wdt[(k0 + kk) * 64 + o];
        }
        for (int j = tid; j < 16 * 128; j += 256) {
            int kk = j >> 7, c = j & 127;
            int tw = tw0 + c;
            Bs[kk][c] = (tw < TV) ? zb[(size_t)(k0 + kk) * TV + tw] : 0.f;
        }
        __syncthreads();
#pragma unroll
        for (int kk = 0; kk < 16; kk++) {
            float4 b4 = *(const float4*)&Bs[kk][tx * 4];
            float4 a0 = *(const float4*)&As[kk][ty * 8];
            float4 a1 = *(const float4*)&As[kk][ty * 8 + 4];
            float av[8] = {a0.x, a0.y, a0.z, a0.w, a1.x, a1.y, a1.z, a1.w};
            float bv[4] = {b4.x, b4.y, b4.z, b4.w};
#pragma unroll
            for (int r = 0; r < 8; r++)
#pragma unroll
                for (int q = 0; q < 4; q++) acc[r][q] += av[r] * bv[q];
        }
    }
    // epilogue
#pragma unroll
    for (int r = 0; r < 8; r++) {
        int o = ty * 8 + r;
        float bias = g_bdsum[o];
        float* yp = g_y + (size_t)(n * Cc + o) * TV;
#pragma unroll
        for (int q = 0; q < 4; q++) {
            int tw = tw0 + tx * 4 + q;
            if (tw < TV) yp[tw] = acc[r][q] + bias;
        }
    }
}

// ---------------- K6: BN statistics (sum, sumsq per channel) -------------------
// grid (64, 24), block 256; 20000 elems per block.
__global__ void k_stats() {
    int o = blockIdx.x;
    int e0 = blockIdx.y * 20000;
    float s1 = 0.f, s2 = 0.f;
    for (int e = e0 + threadIdx.x; e < e0 + 20000; e += 256) {
        int n = e / TV, tw = e - n * TV;
        float v = g_y[(size_t)(n * Cc + o) * TV + tw];
        s1 += v; s2 += v * v;
    }
    __shared__ float r1[256], r2[256];
    r1[threadIdx.x] = s1; r2[threadIdx.x] = s2;
    __syncthreads();
    for (int d = 128; d > 0; d >>= 1) {
        if (threadIdx.x < d) { r1[threadIdx.x] += r1[threadIdx.x + d]; r2[threadIdx.x] += r2[threadIdx.x + d]; }
        __syncthreads();
    }
    if (threadIdx.x == 0) {
        atomicAdd(&g_stats[o], r1[0]);
        atomicAdd(&g_stats[64 + o], r2[0]);
    }
}

// ---------------- K7: normalize + beta/gamma + residual + relu ----------------
// grid 30000, block 256; one float4 per thread (channel constant within float4).
__global__ void k_final(const float* __restrict__ x,
                        const float* __restrict__ gamma, const float* __restrict__ beta,
                        float* __restrict__ out) {
    int i4 = blockIdx.x * 256 + threadIdx.x;        // 7,680,000 float4s
    int c = (i4 / 1875) & 63;                        // TV/4 = 1875
    float s1 = g_stats[c], s2 = g_stats[64 + c];
    float mean = s1 / CNT_BN;
    float var = s2 / CNT_BN - mean * mean;
    float scale = gamma[c] * rsqrtf(var + EPS_BN);
    float bet = beta[c];
    float4 yv = ((const float4*)g_y)[i4];
    float4 xv = ((const float4*)x)[i4];
    float4 o;
    o.x = fmaxf(0.f, (yv.x - mean) * scale + bet + xv.x);
    o.y = fmaxf(0.f, (yv.y - mean) * scale + bet + xv.y);
    o.z = fmaxf(0.f, (yv.z - mean) * scale + bet + xv.z);
    o.w = fmaxf(0.f, (yv.w - mean) * scale + bet + xv.w);
    ((float4*)out)[i4] = o;
}

// ---------------- launch ------------------------------------------------------
extern "C" void kernel_launch(void* const* d_in, const int* in_sizes, int n_in,
                              void* d_out, int out_size) {
    const float* x     = (const float*)d_in[0];
    const float* A     = (const float*)d_in[1];
    const float* W     = (const float*)d_in[2];
    const float* wa    = (const float*)d_in[3];
    const float* ba    = (const float*)d_in[4];
    const float* wb    = (const float*)d_in[5];
    const float* bb    = (const float*)d_in[6];
    const float* wd    = (const float*)d_in[7];
    const float* bd    = (const float*)d_in[8];
    const float* gamma = (const float*)d_in[9];
    const float* beta  = (const float*)d_in[10];
    float* out = (float*)d_out;

    static bool attr_set = false;
    if (!attr_set) {
        cudaFuncSetAttribute(k_z, cudaFuncAttributeMaxDynamicSharedMemorySize, 56 * 1024);
        attr_set = true;
    }

    k_prep<<<472, 256>>>(wd, bd);
    k_ab<<<dim3(NS, 15), 256>>>(x, wa, ba, wb, bb);
    k_scores<<<dim3(NS, 4), 256>>>();
    k_softmax<<<NS, 32>>>(A, W);
    k_z<<<dim3(NS, 10), 256, (640 + 8 * 1600) * sizeof(float)>>>(x);
    k_gemm<<<dim3(Nn, 59), 256>>>();
    k_stats<<<dim3(Cc, 24), 256>>>();
    k_final<<<30000, 256>>>(x, gamma, beta, out);
}